// round 7
// baseline (speedup 1.0000x reference)
#include <cuda_runtime.h>

// MeanAggregator: out[b] = mean over DISTINCT sampled neighbors of features[nbrs[b,s]]
// features: float32 [N=200000, D=256]   (d_in[0])
// nbrs:     int32   [B=32768, S=10]     (d_in[1])
// out:      float32 [B, D]              (d_out)
//
// Consolidated best configuration (DRAM-roofline-bound at ~5.9 TB/s):
//  - 64 lanes per row, one float4 gather per (lane, sample): 8x128B fully
//    coalesced lines per feature row, 10 independent loads in flight/thread.
//  - __ldcg: L2-only (no reuse below L2).
//  - dup weights as a 10-bit mask; regs capped for full occupancy.
//  - 256-bit streaming stores: lane pairs emit STG.E.256, halving store
//    wavefronts and write-burst turnarounds.

#define D 256
#define S 10
#define LANES 64
#define ROWS_PER_CTA 4

__global__ __launch_bounds__(LANES * ROWS_PER_CTA, 8)
void mean_agg_kernel(const float* __restrict__ feat,
                     const int* __restrict__ nbrs,
                     float* __restrict__ out,
                     int B)
{
    const int row  = blockIdx.x * ROWS_PER_CTA + threadIdx.y;  // grid exact
    const int lane = threadIdx.x;            // 0..63, owns floats [lane*4, lane*4+4)

    // Vectorized index load: 40 bytes per row, 8-byte aligned -> 5x int2.
    const int2* __restrict__ nb2 =
        reinterpret_cast<const int2*>(nbrs + (long long)row * S);
    int idx[S];
#pragma unroll
    for (int i = 0; i < 5; ++i) {
        int2 p = nb2[i];
        idx[2 * i]     = p.x;
        idx[2 * i + 1] = p.y;
    }

    // Dup mask: bit i set if idx[i] repeats an earlier index. 45 compares.
    unsigned mask = 0;
    float n = 0.f;
#pragma unroll
    for (int i = 0; i < S; ++i) {
        bool dup = false;
#pragma unroll
        for (int j = 0; j < i; ++j) dup |= (idx[j] == idx[i]);
        mask |= dup ? (1u << i) : 0u;
        n += dup ? 0.f : 1.f;
    }

    // Unconditional weighted gathers (L2-only). 10 independent LDG.128.
    float4 acc = make_float4(0.f, 0.f, 0.f, 0.f);
#pragma unroll
    for (int i = 0; i < S; ++i) {
        const float4 v = __ldcg(reinterpret_cast<const float4*>(
            feat + (long long)idx[i] * D + lane * 4));
        const float wi = (mask & (1u << i)) ? 0.f : 1.f;
        acc.x = fmaf(wi, v.x, acc.x);
        acc.y = fmaf(wi, v.y, acc.y);
        acc.z = fmaf(wi, v.z, acc.z);
        acc.w = fmaf(wi, v.w, acc.w);
    }

    const float inv = 1.f / n;
    float o0 = acc.x * inv;
    float o1 = acc.y * inv;
    float o2 = acc.z * inv;
    float o3 = acc.w * inv;

    // 256-bit streaming store: even lane stores its own 16B + odd partner's
    // 16B as one STG.E.256 (pair exchanges via shfl; output never re-read).
    const unsigned full = 0xFFFFFFFFu;
    float p0 = __shfl_xor_sync(full, o0, 1);
    float p1 = __shfl_xor_sync(full, o1, 1);
    float p2 = __shfl_xor_sync(full, o2, 1);
    float p3 = __shfl_xor_sync(full, o3, 1);
    if ((lane & 1) == 0) {
        float* dst = out + (long long)row * D + lane * 4;   // 32B aligned
        asm volatile("st.global.cs.v8.f32 [%0], {%1,%2,%3,%4,%5,%6,%7,%8};"
                     :: "l"(dst),
                        "f"(o0), "f"(o1), "f"(o2), "f"(o3),
                        "f"(p0), "f"(p1), "f"(p2), "f"(p3)
                     : "memory");
    }
}

extern "C" void kernel_launch(void* const* d_in, const int* in_sizes, int n_in,
                              void* d_out, int out_size)
{
    const float* feat = (const float*)d_in[0];
    const int*   nbrs = (const int*)d_in[1];
    float*       out  = (float*)d_out;

    const int B = in_sizes[1] / S;           // 32768

    dim3 block(LANES, ROWS_PER_CTA);
    dim3 grid(B / ROWS_PER_CTA);
    mean_agg_kernel<<<grid, block>>>(feat, nbrs, out, B);
}